// round 7
// baseline (speedup 1.0000x reference)
#include <cuda_runtime.h>
#include <math.h>
#include <stdint.h>

#define BNUM 32
#define LLT 512
#define LST 128
#define CIN 9
#define HDIM 128
#define RNUM 8
#define KWIN 25
#define PADW 12
#define EPSF 1e-5f
#define OUTC 192   // M*3
#define NHTOT 16384  // LST*HDIM
#define NCHUNK 64    // nh chunks of 256

typedef unsigned long long u64;

// -------- scratch (static device, no allocs) --------
__device__ float d_bufA[BNUM*LLT*HDIM];
__device__ float d_bufB[BNUM*LLT*HDIM];
__device__ float d_est [BNUM*LST*HDIM];
__device__ float d_lbpart[4*BNUM*HDIM*256];   // K-split partials, 16MB
__device__ float d_logits[BNUM*RNUM];
__device__ float d_wsel[BNUM];
__device__ int   d_rcount[RNUM];
__device__ int   d_rlist[RNUM*BNUM];
__device__ float d_partial[BNUM*NCHUNK*OUTC];

// -------- f32x2 packed math helpers --------
__device__ __forceinline__ u64 pack2(float lo, float hi){
    u64 d;
    asm("mov.b64 %0, {%1, %2};" : "=l"(d)
        : "r"(__float_as_uint(lo)), "r"(__float_as_uint(hi)));
    return d;
}
__device__ __forceinline__ void unpack2(u64 v, float& lo, float& hi){
    uint32_t a, b;
    asm("mov.b64 {%0, %1}, %2;" : "=r"(a), "=r"(b) : "l"(v));
    lo = __uint_as_float(a); hi = __uint_as_float(b);
}
__device__ __forceinline__ void ffma2(u64& d, u64 a, u64 b, u64 c){
    asm("fma.rn.f32x2 %0, %1, %2, %3;" : "=l"(d) : "l"(a), "l"(b), "l"(c));
}

__device__ __forceinline__ float gelu_exact(float x){
    return 0.5f*x*(1.0f+erff(x*0.7071067811865476f));
}

// reduce 4 values over the NQ threads of each tid-contiguous group (NQ = 32/64/128/256)
// buf must hold (blockDim/32)*4 floats when NQ>32; all block threads must call.
template<int NQ>
__device__ __forceinline__ void grp_reduce4(float v[4], float* buf, int tid){
    #pragma unroll
    for (int i=0;i<4;i++){
        #pragma unroll
        for (int o=16; o; o>>=1) v[i] += __shfl_xor_sync(0xffffffffu, v[i], o);
    }
    if (NQ > 32){
        constexpr int NWG = NQ/32;
        int wid = tid>>5, lane = tid&31;
        if (lane==0){
            #pragma unroll
            for (int i=0;i<4;i++) buf[wid*4+i] = v[i];
        }
        __syncthreads();
        int gw0 = (wid/NWG)*NWG;
        #pragma unroll
        for (int i=0;i<4;i++){
            float s = 0.f;
            #pragma unroll
            for (int w=0;w<NWG;w++) s += buf[(gw0+w)*4+i];
            v[i] = s;
        }
        __syncthreads();
    }
}

// ---------------- encode: warp-per-l; x-=x[:,0]; moving avg; two LBR branches ----------------
__global__ void encode_kernel(const float* __restrict__ in,
                              const float* __restrict__ Ws, const float* __restrict__ bs,
                              const float* __restrict__ Wt, const float* __restrict__ bt,
                              float* __restrict__ out, int L){
    int b = blockIdx.y;
    int w = threadIdx.x >> 5, lane = threadIdx.x & 31;
    int l = blockIdx.x*4 + w;
    const float* base = in + (size_t)b*L*CIN;
    float sxl = 0.f, txl = 0.f;
    if (lane < CIN){
        int c = lane;
        float x0 = base[c];
        float xl = base[l*CIN + c];
        float sum = 0.f;
        #pragma unroll
        for (int k=0; k<KWIN; k++){
            int l2 = l - PADW + k;
            l2 = l2 < 0 ? 0 : (l2 > L-1 ? L-1 : l2);
            sum += base[l2*CIN + c];
        }
        float mavg = sum*(1.0f/KWIN);
        sxl = xl - mavg;        // seasonal input
        txl = mavg - x0;        // trend input
    }
    float sx[CIN], tx[CIN];
    #pragma unroll
    for (int c=0;c<CIN;c++){
        sx[c] = __shfl_sync(0xffffffffu, sxl, c);
        tx[c] = __shfl_sync(0xffffffffu, txl, c);
    }
    int h0 = lane*4;
    float4 bsv = *(const float4*)(bs + h0);
    float4 btv = *(const float4*)(bt + h0);
    float s4[4] = {bsv.x, bsv.y, bsv.z, bsv.w};
    float t4[4] = {btv.x, btv.y, btv.z, btv.w};
    #pragma unroll
    for (int c=0;c<CIN;c++){
        float4 wsv = *(const float4*)(Ws + c*HDIM + h0);
        float4 wtv = *(const float4*)(Wt + c*HDIM + h0);
        s4[0]=fmaf(sx[c],wsv.x,s4[0]); s4[1]=fmaf(sx[c],wsv.y,s4[1]);
        s4[2]=fmaf(sx[c],wsv.z,s4[2]); s4[3]=fmaf(sx[c],wsv.w,s4[3]);
        t4[0]=fmaf(tx[c],wtv.x,t4[0]); t4[1]=fmaf(tx[c],wtv.y,t4[1]);
        t4[2]=fmaf(tx[c],wtv.z,t4[2]); t4[3]=fmaf(tx[c],wtv.w,t4[3]);
    }
    float ss = s4[0]+s4[1]+s4[2]+s4[3];
    float ts = t4[0]+t4[1]+t4[2]+t4[3];
    #pragma unroll
    for (int o=16;o;o>>=1){
        ss += __shfl_xor_sync(0xffffffffu, ss, o);
        ts += __shfl_xor_sync(0xffffffffu, ts, o);
    }
    float ms = ss*(1.0f/HDIM), mt = ts*(1.0f/HDIM);
    float ds[4], dt[4];
    float sqs = 0.f, sqt = 0.f;
    #pragma unroll
    for (int i=0;i<4;i++){
        ds[i]=s4[i]-ms; dt[i]=t4[i]-mt;
        sqs = fmaf(ds[i],ds[i],sqs); sqt = fmaf(dt[i],dt[i],sqt);
    }
    #pragma unroll
    for (int o=16;o;o>>=1){
        sqs += __shfl_xor_sync(0xffffffffu, sqs, o);
        sqt += __shfl_xor_sync(0xffffffffu, sqt, o);
    }
    float rs = rsqrtf(sqs*(1.0f/HDIM)+EPSF);
    float rt = rsqrtf(sqt*(1.0f/HDIM)+EPSF);
    float4 y;
    y.x = gelu_exact(ds[0]*rs) + gelu_exact(dt[0]*rt);
    y.y = gelu_exact(ds[1]*rs) + gelu_exact(dt[1]*rt);
    y.z = gelu_exact(ds[2]*rs) + gelu_exact(dt[2]*rt);
    y.w = gelu_exact(ds[3]*rs) + gelu_exact(dt[3]*rt);
    *(float4*)(out + ((size_t)b*L + l)*HDIM + h0) = y;
}

// ---------------- hidden LBR: out[i,j] = gelu(inorm_j(x[i,:]@W[:,j]+b)) ----------------
// 2j x 4i register tile. NJP=64 j-pairs, G=2 i-groups of 4 -> 128 threads, 8 rows/block.
__global__ void hidden_kernel(const float* __restrict__ in, const float* __restrict__ W,
                              const float* __restrict__ bias, float* __restrict__ out, int L){
    constexpr int NJP = 64, G = 2, NT = NJP*G, RPB = 4*G;  // 8 rows/block
    int tid = threadIdx.x;
    int q = tid % NJP, g = tid / NJP;
    int j0 = 2*q;
    int ibase = blockIdx.x * RPB;
    int b = blockIdx.y;
    __shared__ __align__(16) float xs[HDIM*RPB];   // [k][row] natural, 4KB
    __shared__ float rbuf[(NT/32)*4];
    const float* basein = in + ((size_t)b*L + ibase)*HDIM;
    for (int e = tid; e < RPB*HDIM; e += NT){
        int row = e / HDIM, k = e % HDIM;
        xs[k*RPB + row] = basein[(size_t)row*HDIM + k];
    }
    __syncthreads();
    float2 bv = *(const float2*)(bias + j0);
    u64 acc[2][2];   // [ipair][j]
    acc[0][0] = pack2(bv.x, bv.x); acc[1][0] = acc[0][0];
    acc[0][1] = pack2(bv.y, bv.y); acc[1][1] = acc[0][1];
    #pragma unroll 8
    for (int k=0;k<HDIM;k++){
        float2 w2 = *(const float2*)(W + (size_t)k*HDIM + j0);
        ulonglong2 xa = *(const ulonglong2*)(xs + k*RPB + g*4);  // rows g*4..g*4+3
        u64 w0d = pack2(w2.x, w2.x);
        u64 w1d = pack2(w2.y, w2.y);
        ffma2(acc[0][0], xa.x, w0d, acc[0][0]);
        ffma2(acc[1][0], xa.y, w0d, acc[1][0]);
        ffma2(acc[0][1], xa.x, w1d, acc[0][1]);
        ffma2(acc[1][1], xa.y, w1d, acc[1][1]);
    }
    float val[4][2];   // [i local][j]
    unpack2(acc[0][0], val[0][0], val[1][0]);
    unpack2(acc[1][0], val[2][0], val[3][0]);
    unpack2(acc[0][1], val[0][1], val[1][1]);
    unpack2(acc[1][1], val[2][1], val[3][1]);
    float v[4];
    #pragma unroll
    for (int i=0;i<4;i++) v[i] = val[i][0] + val[i][1];
    grp_reduce4<NJP>(v, rbuf, tid);
    float mean[4];
    #pragma unroll
    for (int i=0;i<4;i++) mean[i] = v[i]*(1.0f/HDIM);
    float d[4][2];
    #pragma unroll
    for (int i=0;i<4;i++){
        d[i][0] = val[i][0]-mean[i];
        d[i][1] = val[i][1]-mean[i];
        v[i] = fmaf(d[i][0],d[i][0], d[i][1]*d[i][1]);
    }
    grp_reduce4<NJP>(v, rbuf, tid);
    #pragma unroll
    for (int i=0;i<4;i++){
        float rv = rsqrtf(v[i]*(1.0f/HDIM)+EPSF);
        float2 o2;
        o2.x = gelu_exact(d[i][0]*rv);
        o2.y = gelu_exact(d[i][1]*rv);
        *(float2*)(out + ((size_t)b*L + ibase + g*4 + i)*HDIM + j0) = o2;
    }
}

// ---------------- lookback partial: raw GEMM chunk, 4j x 4h tile, K-split ----------------
// part[ks][b][h][j] = sum_{l in chunk ks} x[b][l][h] * W[l][j]
template<int LIN, int LOUT, int HPB, int KS>
__global__ void lookback_partial(const float* __restrict__ in, const float* __restrict__ W,
                                 float* __restrict__ part){
    constexpr int NJQ = LOUT/4;
    constexpr int KCH = LIN/KS;
    constexpr int NT = NJQ*(HPB/4);
    int tid = threadIdx.x;
    int q = tid % NJQ, g = tid / NJQ;
    int j0 = 4*q, h0 = 4*g;
    int hbase = blockIdx.x * HPB;
    int ks = blockIdx.y;
    int b  = blockIdx.z;
    int k0 = ks*KCH;
    __shared__ __align__(16) float xs[KCH*HPB];   // [l_local][h_local], 8KB
    const float* basein = in + ((size_t)b*LIN + k0)*HDIM + hbase;
    for (int e = tid; e < KCH*HPB/4; e += NT){
        int l = e / (HPB/4), hf = e % (HPB/4);
        *(float4*)(xs + l*HPB + 4*hf) = *(const float4*)(basein + (size_t)l*HDIM + 4*hf);
    }
    __syncthreads();
    u64 acc[2][4];   // [hpair][j]
    #pragma unroll
    for (int hp=0;hp<2;hp++)
        #pragma unroll
        for (int j=0;j<4;j++) acc[hp][j]=0ull;
    const float* Wp = W + (size_t)k0*LOUT + j0;
    #pragma unroll 4
    for (int l=0;l<KCH;l++){
        float4 w4 = *(const float4*)(Wp + (size_t)l*LOUT);
        ulonglong2 xp = *(const ulonglong2*)(xs + l*HPB + h0);  // (h0,h0+1),(h0+2,h0+3)
        u64 wd0 = pack2(w4.x,w4.x), wd1 = pack2(w4.y,w4.y);
        u64 wd2 = pack2(w4.z,w4.z), wd3 = pack2(w4.w,w4.w);
        ffma2(acc[0][0], xp.x, wd0, acc[0][0]);
        ffma2(acc[0][1], xp.x, wd1, acc[0][1]);
        ffma2(acc[0][2], xp.x, wd2, acc[0][2]);
        ffma2(acc[0][3], xp.x, wd3, acc[0][3]);
        ffma2(acc[1][0], xp.y, wd0, acc[1][0]);
        ffma2(acc[1][1], xp.y, wd1, acc[1][1]);
        ffma2(acc[1][2], xp.y, wd2, acc[1][2]);
        ffma2(acc[1][3], xp.y, wd3, acc[1][3]);
    }
    float val[4][4];   // [h local][j local]
    #pragma unroll
    for (int hp=0;hp<2;hp++)
        #pragma unroll
        for (int j=0;j<4;j++)
            unpack2(acc[hp][j], val[2*hp][j], val[2*hp+1][j]);
    float* pb = part + ((size_t)(ks*BNUM + b)*HDIM + hbase + h0)*LOUT + j0;
    #pragma unroll
    for (int h=0;h<4;h++)
        *(float4*)(pb + (size_t)h*LOUT) = make_float4(val[h][0],val[h][1],val[h][2],val[h][3]);
}

// ---------------- lookback finalize: sum partials + bias, inorm over j, gelu, transpose ----------------
template<int LOUT, int KS>
__global__ void lookback_finalize(const float* __restrict__ part, const float* __restrict__ bias,
                                  float* __restrict__ out){
    int t = threadIdx.x;          // t = j, blockDim = LOUT
    int h0 = blockIdx.x*4;
    int b  = blockIdx.y;
    __shared__ float rbuf[(LOUT/32)*4];
    float bj = bias[t];
    float val[4];
    #pragma unroll
    for (int h=0;h<4;h++){
        float s = bj;
        #pragma unroll
        for (int ks=0;ks<KS;ks++)
            s += part[((size_t)(ks*BNUM + b)*HDIM + h0 + h)*LOUT + t];
        val[h]=s;
    }
    float v[4] = {val[0],val[1],val[2],val[3]};
    grp_reduce4<LOUT>(v, rbuf, t);
    float d[4];
    #pragma unroll
    for (int h=0;h<4;h++) d[h] = val[h] - v[h]*(1.0f/LOUT);
    float v2[4] = {d[0]*d[0], d[1]*d[1], d[2]*d[2], d[3]*d[3]};
    grp_reduce4<LOUT>(v2, rbuf, t);
    float4 o;
    o.x = gelu_exact(d[0]*rsqrtf(v2[0]*(1.0f/LOUT)+EPSF));
    o.y = gelu_exact(d[1]*rsqrtf(v2[1]*(1.0f/LOUT)+EPSF));
    o.z = gelu_exact(d[2]*rsqrtf(v2[2]*(1.0f/LOUT)+EPSF));
    o.w = gelu_exact(d[3]*rsqrtf(v2[3]*(1.0f/LOUT)+EPSF));
    *(float4*)(out + ((size_t)b*LOUT + t)*HDIM + h0) = o;
}

// ---------------- logits: (B,8192) @ (8192,8) + br ----------------
__global__ void logits_kernel(const float* __restrict__ o, const float* __restrict__ Wr,
                              const float* __restrict__ br, float* __restrict__ logits){
    int b = blockIdx.x, tid = threadIdx.x;  // 256 threads
    float acc[8];
    #pragma unroll
    for (int r=0;r<8;r++) acc[r]=0.f;
    for (int i=tid; i<8192; i+=256){
        float x = o[(size_t)b*8192 + i];
        const float4* w4 = reinterpret_cast<const float4*>(Wr + (size_t)i*8);
        float4 wa = w4[0], wb = w4[1];
        acc[0]=fmaf(x,wa.x,acc[0]); acc[1]=fmaf(x,wa.y,acc[1]);
        acc[2]=fmaf(x,wa.z,acc[2]); acc[3]=fmaf(x,wa.w,acc[3]);
        acc[4]=fmaf(x,wb.x,acc[4]); acc[5]=fmaf(x,wb.y,acc[5]);
        acc[6]=fmaf(x,wb.z,acc[6]); acc[7]=fmaf(x,wb.w,acc[7]);
    }
    __shared__ float sh[8*8];
    #pragma unroll
    for (int r=0;r<8;r++){
        #pragma unroll
        for (int o2=16;o2;o2>>=1) acc[r] += __shfl_xor_sync(0xffffffffu, acc[r], o2);
    }
    int w=tid>>5, lane=tid&31;
    if (lane==0){
        #pragma unroll
        for (int r=0;r<8;r++) sh[r*8+w]=acc[r];
    }
    __syncthreads();
    if (tid<8){
        float s=br[tid];
        #pragma unroll
        for (int ww=0;ww<8;ww++) s+=sh[tid*8+ww];
        logits[b*8+tid]=s;
    }
}

// ---------------- exact JAX threefry2x32 (partitionable) gumbel + hard select + regime lists ----------------
__device__ __forceinline__ uint32_t rotl32(uint32_t x,int r){ return (x<<r)|(x>>(32-r)); }
__device__ __forceinline__ float gumbel_from_bits(uint32_t bits){
    const float tiny = 1.17549435e-38f;
    float f = __uint_as_float((bits>>9)|0x3f800000u) - 1.0f;
    float u = fmaxf(tiny, f + tiny);
    return -logf(-logf(u));
}
__global__ void gumbel_kernel(const float* __restrict__ logits,
                              float* __restrict__ wsel,
                              int* __restrict__ rcount, int* __restrict__ rlist){
    __shared__ float g[256];
    __shared__ int sreg[BNUM];
    int tid = threadIdx.x;  // 256 threads
    {
        uint32_t x0 = 0u, x1 = (uint32_t)tid;
        const uint32_t k0=0u, k1=42u, k2=k0^k1^0x1BD11BDAu;
        x0+=k0; x1+=k1;
        #define TFR(r) { x0+=x1; x1=rotl32(x1,r); x1^=x0; }
        TFR(13)TFR(15)TFR(26)TFR(6)   x0+=k1; x1+=k2+1u;
        TFR(17)TFR(29)TFR(16)TFR(24)  x0+=k2; x1+=k0+2u;
        TFR(13)TFR(15)TFR(26)TFR(6)   x0+=k0; x1+=k1+3u;
        TFR(17)TFR(29)TFR(16)TFR(24)  x0+=k1; x1+=k2+4u;
        TFR(13)TFR(15)TFR(26)TFR(6)   x0+=k2; x1+=k0+5u;
        #undef TFR
        g[tid] = gumbel_from_bits(x0 ^ x1);
    }
    __syncthreads();
    if (tid < BNUM){
        float z[8];
        #pragma unroll
        for (int r=0;r<8;r++) z[r] = logits[tid*8+r] + g[tid*8+r];  // TAU=1
        float mx = z[0]; int am = 0;
        #pragma unroll
        for (int r=1;r<8;r++) if (z[r] > mx){ mx=z[r]; am=r; }
        float sum=0.f;
        #pragma unroll
        for (int r=0;r<8;r++) sum += expf(z[r]-mx);
        float y = 1.0f/sum;
        wsel[tid] = (1.0f - y) + y;
        sreg[tid] = am;
    }
    __syncthreads();
    if (tid == 0){
        int cnt[RNUM];
        #pragma unroll
        for (int r=0;r<RNUM;r++) cnt[r]=0;
        for (int b=0;b<BNUM;b++){
            int r = sreg[b];
            rlist[r*BNUM + cnt[r]] = b;
            cnt[r]++;
        }
        #pragma unroll
        for (int r=0;r<RNUM;r++) rcount[r]=cnt[r];
    }
}

// ---------------- final contraction, regime-grouped, f32x2 over batch pairs ----------------
template<int NP>
__device__ __forceinline__ void fp_body(const u64* __restrict__ es2,
                                        const float* __restrict__ P,
                                        float* __restrict__ partial,
                                        const int* __restrict__ bl,
                                        int nb, int chunk, int t){
    u64 acc[NP];
    #pragma unroll
    for (int q=0;q<NP;q++) acc[q]=0ull;
    #pragma unroll 4
    for (int nh=0; nh<256; nh++){
        float pv = P[(size_t)nh*OUTC];
        u64 pp = pack2(pv, pv);
        const u64* row = es2 + nh*16;
        #pragma unroll
        for (int q=0;q<NP;q++) ffma2(acc[q], row[q], pp, acc[q]);
    }
    #pragma unroll
    for (int q=0;q<NP;q++){
        float lo, hi; unpack2(acc[q], lo, hi);
        partial[((size_t)bl[2*q]*NCHUNK + chunk)*OUTC + t] = lo;
        if (2*q+1 < nb)
            partial[((size_t)bl[2*q+1]*NCHUNK + chunk)*OUTC + t] = hi;
    }
}

__global__ void final_partial(const float* __restrict__ est, const float* __restrict__ proto,
                              const int* __restrict__ rcount, const int* __restrict__ rlist,
                              float* __restrict__ partial){
    int chunk = blockIdx.x, r = blockIdx.y, t = threadIdx.x;  // 192 threads
    int nb = rcount[r];
    if (nb == 0) return;
    int npair = (nb+1)>>1;
    __shared__ __align__(16) u64 es2[256*16];   // [nh][pair] 32KB
    __shared__ int bl[BNUM];
    if (t < BNUM) bl[t] = rlist[r*BNUM + t];
    __syncthreads();
    int nh0 = chunk*256;
    for (int q=0;q<npair;q++){
        int b0 = bl[2*q];
        bool has1 = (2*q+1) < nb;
        const float* e0 = est + (size_t)b0*NHTOT + nh0;
        const float* e1 = has1 ? est + (size_t)bl[2*q+1]*NHTOT + nh0 : e0;
        for (int nh=t; nh<256; nh+=192){
            float lo = e0[nh];
            float hi = has1 ? e1[nh] : 0.f;
            es2[nh*16+q] = pack2(lo, hi);
        }
    }
    __syncthreads();
    const float* P = proto + ((size_t)r*NHTOT + nh0)*OUTC + t;
    switch(npair){
        case 1:  fp_body<1>(es2,P,partial,bl,nb,chunk,t); break;
        case 2:  fp_body<2 >(es2,P,partial,bl,nb,chunk,t); break;
        case 3:  fp_body<3 >(es2,P,partial,bl,nb,chunk,t); break;
        case 4:  fp_body<4 >(es2,P,partial,bl,nb,chunk,t); break;
        case 5:  fp_body<5 >(es2,P,partial,bl,nb,chunk,t); break;
        case 6:  fp_body<6 >(es2,P,partial,bl,nb,chunk,t); break;
        case 7:  fp_body<7 >(es2,P,partial,bl,nb,chunk,t); break;
        case 8:  fp_body<8 >(es2,P,partial,bl,nb,chunk,t); break;
        case 9:  fp_body<9 >(es2,P,partial,bl,nb,chunk,t); break;
        case 10: fp_body<10>(es2,P,partial,bl,nb,chunk,t); break;
        case 11: fp_body<11>(es2,P,partial,bl,nb,chunk,t); break;
        case 12: fp_body<12>(es2,P,partial,bl,nb,chunk,t); break;
        case 13: fp_body<13>(es2,P,partial,bl,nb,chunk,t); break;
        case 14: fp_body<14>(es2,P,partial,bl,nb,chunk,t); break;
        case 15: fp_body<15>(es2,P,partial,bl,nb,chunk,t); break;
        default: fp_body<16>(es2,P,partial,bl,nb,chunk,t); break;
    }
}

__global__ void final_softmax(const float* __restrict__ partial, const float* __restrict__ wsel,
                              float* __restrict__ out){
    int b = blockIdx.x, t = threadIdx.x;  // 192 threads = 6 warps
    float s = 0.f;
    #pragma unroll 8
    for (int ch=0; ch<NCHUNK; ch++) s += partial[((size_t)b*NCHUNK+ch)*OUTC + t];
    s *= wsel[b];
    __shared__ float shm[6], shs[6];
    float m = s;
    #pragma unroll
    for (int o=16;o;o>>=1) m = fmaxf(m, __shfl_xor_sync(0xffffffffu, m, o));
    if ((t&31)==0) shm[t>>5]=m;
    __syncthreads();
    m = shm[0];
    #pragma unroll
    for (int w=1;w<6;w++) m = fmaxf(m, shm[w]);
    float e = expf(s-m);
    float su = e;
    #pragma unroll
    for (int o=16;o;o>>=1) su += __shfl_xor_sync(0xffffffffu, su, o);
    if ((t&31)==0) shs[t>>5]=su;
    __syncthreads();
    su = 0.f;
    #pragma unroll
    for (int w=0;w<6;w++) su += shs[w];
    out[(size_t)b*OUTC + t] = e/su;
}

// ---------------- launch ----------------
extern "C" void kernel_launch(void* const* d_in, const int* in_sizes, int n_in,
                              void* d_out, int out_size){
    (void)in_sizes; (void)n_in; (void)out_size;
    const float* in_lt = (const float*)d_in[0];
    const float* in_st = (const float*)d_in[1];
    const float* Ws  = (const float*)d_in[2];  const float* bs  = (const float*)d_in[3];
    const float* Wt  = (const float*)d_in[4];  const float* bt  = (const float*)d_in[5];
    const float* Wh1 = (const float*)d_in[6];  const float* bh1 = (const float*)d_in[7];
    const float* Wl1 = (const float*)d_in[8];  const float* bl1 = (const float*)d_in[9];
    const float* Wh2 = (const float*)d_in[10]; const float* bh2 = (const float*)d_in[11];
    const float* Wl2 = (const float*)d_in[12]; const float* bl2 = (const float*)d_in[13];
    const float* Wh3 = (const float*)d_in[14]; const float* bh3 = (const float*)d_in[15];
    const float* Wl3 = (const float*)d_in[16]; const float* bl3 = (const float*)d_in[17];
    const float* Wr  = (const float*)d_in[18]; const float* br  = (const float*)d_in[19];
    const float* proto = (const float*)d_in[20];

    float *bufA, *bufB, *est, *lbpart, *logits, *wsel, *partial; int *rcount, *rlist;
    cudaGetSymbolAddress((void**)&bufA,    d_bufA);
    cudaGetSymbolAddress((void**)&bufB,    d_bufB);
    cudaGetSymbolAddress((void**)&est,     d_est);
    cudaGetSymbolAddress((void**)&lbpart,  d_lbpart);
    cudaGetSymbolAddress((void**)&logits,  d_logits);
    cudaGetSymbolAddress((void**)&wsel,    d_wsel);
    cudaGetSymbolAddress((void**)&rcount,  d_rcount);
    cudaGetSymbolAddress((void**)&rlist,   d_rlist);
    cudaGetSymbolAddress((void**)&partial, d_partial);

    encode_kernel<<<dim3(LLT/4,BNUM), 128>>>(in_lt, Ws, bs, Wt, bt, bufA, LLT);
    encode_kernel<<<dim3(LST/4,BNUM), 128>>>(in_st, Ws, bs, Wt, bt, est,  LST);

    hidden_kernel<<<dim3(LLT/8,BNUM), 128>>>(bufA, Wh1, bh1, bufB, LLT);
    lookback_partial<512,256,16,4><<<dim3(8,4,BNUM), 256>>>(bufB, Wl1, lbpart);
    lookback_finalize<256,4><<<dim3(HDIM/4,BNUM), 256>>>(lbpart, bl1, bufA);

    hidden_kernel<<<dim3(256/8,BNUM), 128>>>(bufA, Wh2, bh2, bufB, 256);
    lookback_partial<256,128,32,4><<<dim3(4,4,BNUM), 256>>>(bufB, Wl2, lbpart);
    lookback_finalize<128,4><<<dim3(HDIM/4,BNUM), 128>>>(lbpart, bl2, bufA);

    hidden_kernel<<<dim3(128/8,BNUM), 128>>>(bufA, Wh3, bh3, bufB, 128);
    lookback_partial<128,64,64,4><<<dim3(2,4,BNUM), 256>>>(bufB, Wl3, lbpart);
    lookback_finalize<64,4><<<dim3(HDIM/4,BNUM), 64>>>(lbpart, bl3, bufA);

    logits_kernel<<<BNUM, 256>>>(bufA, Wr, br, logits);
    gumbel_kernel<<<1, 256>>>(logits, wsel, rcount, rlist);

    final_partial<<<dim3(NCHUNK,RNUM), OUTC>>>(est, proto, rcount, rlist, partial);
    final_softmax<<<BNUM, OUTC>>>(partial, wsel, (float*)d_out);
}

// round 8
// speedup vs baseline: 1.1586x; 1.1586x over previous
#include <cuda_runtime.h>
#include <math.h>
#include <stdint.h>

#define BNUM 32
#define LLT 512
#define LST 128
#define CIN 9
#define HDIM 128
#define RNUM 8
#define KWIN 25
#define PADW 12
#define EPSF 1e-5f
#define OUTC 192   // M*3
#define NHTOT 16384  // LST*HDIM
#define NCHUNK 64    // nh chunks of 256

typedef unsigned long long u64;

// -------- scratch (static device, no allocs) --------
__device__ float d_bufA[BNUM*LLT*HDIM];
__device__ float d_bufB[BNUM*LLT*HDIM];
__device__ float d_est [BNUM*LST*HDIM];
__device__ float d_logits[BNUM*RNUM];
__device__ float d_wsel[BNUM];
__device__ int   d_rcount[RNUM];
__device__ int   d_rlist[RNUM*BNUM];
__device__ float d_partial[BNUM*NCHUNK*OUTC];

// -------- f32x2 packed math helpers --------
__device__ __forceinline__ u64 pack2(float lo, float hi){
    u64 d;
    asm("mov.b64 %0, {%1, %2};" : "=l"(d)
        : "r"(__float_as_uint(lo)), "r"(__float_as_uint(hi)));
    return d;
}
__device__ __forceinline__ void unpack2(u64 v, float& lo, float& hi){
    uint32_t a, b;
    asm("mov.b64 {%0, %1}, %2;" : "=r"(a), "=r"(b) : "l"(v));
    lo = __uint_as_float(a); hi = __uint_as_float(b);
}
__device__ __forceinline__ void ffma2(u64& d, u64 a, u64 b, u64 c){
    asm("fma.rn.f32x2 %0, %1, %2, %3;" : "=l"(d) : "l"(a), "l"(b), "l"(c));
}

__device__ __forceinline__ float gelu_exact(float x){
    return 0.5f*x*(1.0f+erff(x*0.7071067811865476f));
}

// ---------------- encode: warp-per-l; x-=x[:,0]; moving avg; two LBR branches ----------------
__global__ void encode_kernel(const float* __restrict__ in,
                              const float* __restrict__ Ws, const float* __restrict__ bs,
                              const float* __restrict__ Wt, const float* __restrict__ bt,
                              float* __restrict__ out, int L){
    int b = blockIdx.y;
    int w = threadIdx.x >> 5, lane = threadIdx.x & 31;
    int l = blockIdx.x*4 + w;
    const float* base = in + (size_t)b*L*CIN;
    float sxl = 0.f, txl = 0.f;
    if (lane < CIN){
        int c = lane;
        float x0 = base[c];
        float xl = base[l*CIN + c];
        float sum = 0.f;
        #pragma unroll
        for (int k=0; k<KWIN; k++){
            int l2 = l - PADW + k;
            l2 = l2 < 0 ? 0 : (l2 > L-1 ? L-1 : l2);
            sum += base[l2*CIN + c];
        }
        float mavg = sum*(1.0f/KWIN);
        sxl = xl - mavg;        // seasonal input
        txl = mavg - x0;        // trend input
    }
    float sx[CIN], tx[CIN];
    #pragma unroll
    for (int c=0;c<CIN;c++){
        sx[c] = __shfl_sync(0xffffffffu, sxl, c);
        tx[c] = __shfl_sync(0xffffffffu, txl, c);
    }
    int h0 = lane*4;
    float4 bsv = *(const float4*)(bs + h0);
    float4 btv = *(const float4*)(bt + h0);
    float s4[4] = {bsv.x, bsv.y, bsv.z, bsv.w};
    float t4[4] = {btv.x, btv.y, btv.z, btv.w};
    #pragma unroll
    for (int c=0;c<CIN;c++){
        float4 wsv = *(const float4*)(Ws + c*HDIM + h0);
        float4 wtv = *(const float4*)(Wt + c*HDIM + h0);
        s4[0]=fmaf(sx[c],wsv.x,s4[0]); s4[1]=fmaf(sx[c],wsv.y,s4[1]);
        s4[2]=fmaf(sx[c],wsv.z,s4[2]); s4[3]=fmaf(sx[c],wsv.w,s4[3]);
        t4[0]=fmaf(tx[c],wtv.x,t4[0]); t4[1]=fmaf(tx[c],wtv.y,t4[1]);
        t4[2]=fmaf(tx[c],wtv.z,t4[2]); t4[3]=fmaf(tx[c],wtv.w,t4[3]);
    }
    float ss = s4[0]+s4[1]+s4[2]+s4[3];
    float ts = t4[0]+t4[1]+t4[2]+t4[3];
    #pragma unroll
    for (int o=16;o;o>>=1){
        ss += __shfl_xor_sync(0xffffffffu, ss, o);
        ts += __shfl_xor_sync(0xffffffffu, ts, o);
    }
    float ms = ss*(1.0f/HDIM), mt = ts*(1.0f/HDIM);
    float ds[4], dt[4];
    float sqs = 0.f, sqt = 0.f;
    #pragma unroll
    for (int i=0;i<4;i++){
        ds[i]=s4[i]-ms; dt[i]=t4[i]-mt;
        sqs = fmaf(ds[i],ds[i],sqs); sqt = fmaf(dt[i],dt[i],sqt);
    }
    #pragma unroll
    for (int o=16;o;o>>=1){
        sqs += __shfl_xor_sync(0xffffffffu, sqs, o);
        sqt += __shfl_xor_sync(0xffffffffu, sqt, o);
    }
    float rs = rsqrtf(sqs*(1.0f/HDIM)+EPSF);
    float rt = rsqrtf(sqt*(1.0f/HDIM)+EPSF);
    float4 y;
    y.x = gelu_exact(ds[0]*rs) + gelu_exact(dt[0]*rt);
    y.y = gelu_exact(ds[1]*rs) + gelu_exact(dt[1]*rt);
    y.z = gelu_exact(ds[2]*rs) + gelu_exact(dt[2]*rt);
    y.w = gelu_exact(ds[3]*rs) + gelu_exact(dt[3]*rt);
    *(float4*)(out + ((size_t)b*L + l)*HDIM + h0) = y;
}

// ---------------- hidden LBR (R4 layout + chunked prefetch) ----------------
// thread h owns output column h for 8 rows; x dup... natural-paired per column in smem.
// Inner loop: chunk of 2 k -> 2 LDG.32 + 4 LDS.128 batched, then 8 FFMA2.
__global__ void hidden_kernel(const float* __restrict__ in, const float* __restrict__ W,
                              const float* __restrict__ bias, float* __restrict__ out, int L){
    constexpr int ROWS = 8, PR = 4;
    int lg = blockIdx.x, b = blockIdx.y, h = threadIdx.x;  // 128 threads
    __shared__ __align__(16) u64 xs2[HDIM*PR];        // [k][pair i] 4KB
    __shared__ float tmp[ROWS*4];
    __shared__ float res[ROWS], res2[ROWS];
    const float* basein = in + ((size_t)b*L + (size_t)lg*ROWS)*HDIM;
    float* xsF = (float*)xs2;
    #pragma unroll
    for (int i=0;i<ROWS;i++) xsF[h*ROWS + i] = basein[i*HDIM + h];
    __syncthreads();
    float bh = bias[h];
    u64 bp = pack2(bh, bh);
    u64 acc[PR];
    #pragma unroll
    for (int p=0;p<PR;p++) acc[p]=bp;
    #pragma unroll 2
    for (int kc=0;kc<HDIM;kc+=2){
        // batched loads first (MLP)
        float w0 = W[(size_t)kc*HDIM + h];
        float w1 = W[(size_t)(kc+1)*HDIM + h];
        ulonglong2 xa = *(const ulonglong2*)(xs2 + (size_t)kc*PR);
        ulonglong2 xb = *(const ulonglong2*)(xs2 + (size_t)kc*PR + 2);
        ulonglong2 xc = *(const ulonglong2*)(xs2 + (size_t)(kc+1)*PR);
        ulonglong2 xd = *(const ulonglong2*)(xs2 + (size_t)(kc+1)*PR + 2);
        u64 wp0 = pack2(w0, w0);
        u64 wp1 = pack2(w1, w1);
        ffma2(acc[0], xa.x, wp0, acc[0]);
        ffma2(acc[1], xa.y, wp0, acc[1]);
        ffma2(acc[2], xb.x, wp0, acc[2]);
        ffma2(acc[3], xb.y, wp0, acc[3]);
        ffma2(acc[0], xc.x, wp1, acc[0]);
        ffma2(acc[1], xc.y, wp1, acc[1]);
        ffma2(acc[2], xd.x, wp1, acc[2]);
        ffma2(acc[3], xd.y, wp1, acc[3]);
    }
    float val[ROWS], v[ROWS];
    #pragma unroll
    for (int p=0;p<PR;p++) unpack2(acc[p], val[2*p], val[2*p+1]);
    // block reduce 8 values over 128 threads (4 warps)
    int tid = h, wid = tid>>5, lane = tid&31;
    #pragma unroll
    for (int i=0;i<ROWS;i++){
        v[i]=val[i];
        #pragma unroll
        for (int o=16;o;o>>=1) v[i] += __shfl_xor_sync(0xffffffffu, v[i], o);
    }
    if (lane==0){
        #pragma unroll
        for (int i=0;i<ROWS;i++) tmp[i*4+wid]=v[i];
    }
    __syncthreads();
    if (tid<ROWS){
        float s=0.f;
        #pragma unroll
        for (int ww=0;ww<4;ww++) s+=tmp[tid*4+ww];
        res[tid]=s;
    }
    __syncthreads();
    float d[ROWS];
    #pragma unroll
    for (int i=0;i<ROWS;i++){
        d[i]=val[i]-res[i]*(1.0f/HDIM);
        v[i]=d[i]*d[i];
        #pragma unroll
        for (int o=16;o;o>>=1) v[i] += __shfl_xor_sync(0xffffffffu, v[i], o);
    }
    if (lane==0){
        #pragma unroll
        for (int i=0;i<ROWS;i++) tmp[i*4+wid]=v[i];
    }
    __syncthreads();
    if (tid<ROWS){
        float s=0.f;
        #pragma unroll
        for (int ww=0;ww<4;ww++) s+=tmp[tid*4+ww];
        res2[tid]=s;
    }
    __syncthreads();
    float* baseout = out + ((size_t)b*L + (size_t)lg*ROWS)*HDIM;
    #pragma unroll
    for (int i=0;i<ROWS;i++)
        baseout[i*HDIM + h] = gelu_exact(d[i]*rsqrtf(res2[i]*(1.0f/HDIM)+EPSF));
}

// ---------------- lookback LBR (R4 layout + chunked prefetch) ----------------
// G row-groups of 4 h per block; blockDim = G*LOUT. Inner loop chunk of 4 l:
// 4 LDG.32 (W) + 4 LDS.128 (x pairs) batched, then 8 FFMA2.
template<int LIN, int LOUT, int G>
__global__ void lookback_kernel(const float* __restrict__ in, const float* __restrict__ W,
                                const float* __restrict__ bias, float* __restrict__ out){
    constexpr int NW = LOUT/32;
    int hg = blockIdx.x, b = blockIdx.y;
    int tid = threadIdx.x;
    int g = tid / LOUT, j = tid % LOUT;
    __shared__ __align__(16) u64 xs2[LIN*2*G];   // [l][pair] natural h-pairs
    __shared__ float tmp[G*4*NW];
    __shared__ float res[G*4], res2[G*4];
    const float* basein = in + (size_t)b*LIN*HDIM;
    int hbase_blk = hg*(4*G);
    for (int idx=tid; idx<LIN*2*G; idx += G*LOUT){
        int l = idx/(2*G); int r = idx%(2*G);
        int h = hbase_blk + r*2;
        float2 v2 = *(const float2*)(basein + (size_t)l*HDIM + h);
        xs2[idx] = pack2(v2.x, v2.y);
    }
    __syncthreads();
    float bj = bias[j];
    u64 acc0 = pack2(bj, bj);
    u64 acc1 = acc0;
    const u64* xbase = xs2 + g*2;
    const float* Wj = W + j;
    #pragma unroll 2
    for (int lc=0; lc<LIN; lc+=4){
        // batched loads first (MLP = 4 LDG + 4 LDS)
        float w4[4];
        #pragma unroll
        for (int u=0;u<4;u++) w4[u] = Wj[(size_t)(lc+u)*LOUT];
        ulonglong2 xp[4];
        #pragma unroll
        for (int u=0;u<4;u++) xp[u] = *(const ulonglong2*)(xbase + (size_t)(lc+u)*(2*G));
        #pragma unroll
        for (int u=0;u<4;u++){
            u64 wp = pack2(w4[u], w4[u]);
            ffma2(acc0, xp[u].x, wp, acc0);
            ffma2(acc1, xp[u].y, wp, acc1);
        }
    }
    float val[4], v[4];
    unpack2(acc0, val[0], val[1]);
    unpack2(acc1, val[2], val[3]);
    // group-local reduce (4 h values over the LOUT threads of this group)
    #pragma unroll
    for (int i=0;i<4;i++){
        v[i]=val[i];
        #pragma unroll
        for (int o=16;o;o>>=1) v[i] += __shfl_xor_sync(0xffffffffu, v[i], o);
    }
    int w0 = tid>>5, wg = w0 % NW;
    if ((tid&31)==0){
        #pragma unroll
        for (int i=0;i<4;i++) tmp[(g*4+i)*NW + wg] = v[i];
    }
    __syncthreads();
    if (tid < G*4){
        float s=0.f;
        #pragma unroll
        for (int ww=0;ww<NW;ww++) s+=tmp[tid*NW+ww];
        res[tid]=s;
    }
    __syncthreads();
    float d[4];
    #pragma unroll
    for (int i=0;i<4;i++){
        d[i]=val[i]-res[g*4+i]*(1.0f/LOUT);
        v[i]=d[i]*d[i];
        #pragma unroll
        for (int o=16;o;o>>=1) v[i] += __shfl_xor_sync(0xffffffffu, v[i], o);
    }
    if ((tid&31)==0){
        #pragma unroll
        for (int i=0;i<4;i++) tmp[(g*4+i)*NW + wg] = v[i];
    }
    __syncthreads();
    if (tid < G*4){
        float s=0.f;
        #pragma unroll
        for (int ww=0;ww<NW;ww++) s+=tmp[tid*NW+ww];
        res2[tid]=s;
    }
    __syncthreads();
    float o4[4];
    #pragma unroll
    for (int i=0;i<4;i++)
        o4[i] = gelu_exact(d[i]*rsqrtf(res2[g*4+i]*(1.0f/LOUT)+EPSF));
    float* po = out + ((size_t)b*LOUT + j)*HDIM + hbase_blk + g*4;
    ((float4*)po)[0] = make_float4(o4[0],o4[1],o4[2],o4[3]);
}

// ---------------- logits: (B,8192) @ (8192,8) + br ----------------
__global__ void logits_kernel(const float* __restrict__ o, const float* __restrict__ Wr,
                              const float* __restrict__ br, float* __restrict__ logits){
    int b = blockIdx.x, tid = threadIdx.x;  // 256 threads
    float acc[8];
    #pragma unroll
    for (int r=0;r<8;r++) acc[r]=0.f;
    for (int i=tid; i<8192; i+=256){
        float x = o[(size_t)b*8192 + i];
        const float4* w4 = reinterpret_cast<const float4*>(Wr + (size_t)i*8);
        float4 wa = w4[0], wb = w4[1];
        acc[0]=fmaf(x,wa.x,acc[0]); acc[1]=fmaf(x,wa.y,acc[1]);
        acc[2]=fmaf(x,wa.z,acc[2]); acc[3]=fmaf(x,wa.w,acc[3]);
        acc[4]=fmaf(x,wb.x,acc[4]); acc[5]=fmaf(x,wb.y,acc[5]);
        acc[6]=fmaf(x,wb.z,acc[6]); acc[7]=fmaf(x,wb.w,acc[7]);
    }
    __shared__ float sh[8*8];
    #pragma unroll
    for (int r=0;r<8;r++){
        #pragma unroll
        for (int o2=16;o2;o2>>=1) acc[r] += __shfl_xor_sync(0xffffffffu, acc[r], o2);
    }
    int w=tid>>5, lane=tid&31;
    if (lane==0){
        #pragma unroll
        for (int r=0;r<8;r++) sh[r*8+w]=acc[r];
    }
    __syncthreads();
    if (tid<8){
        float s=br[tid];
        #pragma unroll
        for (int ww=0;ww<8;ww++) s+=sh[tid*8+ww];
        logits[b*8+tid]=s;
    }
}

// ---------------- exact JAX threefry2x32 (partitionable) gumbel + hard select + regime lists ----------------
__device__ __forceinline__ uint32_t rotl32(uint32_t x,int r){ return (x<<r)|(x>>(32-r)); }
__device__ __forceinline__ float gumbel_from_bits(uint32_t bits){
    const float tiny = 1.17549435e-38f;
    float f = __uint_as_float((bits>>9)|0x3f800000u) - 1.0f;
    float u = fmaxf(tiny, f + tiny);
    return -logf(-logf(u));
}
__global__ void gumbel_kernel(const float* __restrict__ logits,
                              float* __restrict__ wsel,
                              int* __restrict__ rcount, int* __restrict__ rlist){
    __shared__ float g[256];
    __shared__ int sreg[BNUM];
    int tid = threadIdx.x;  // 256 threads
    {
        uint32_t x0 = 0u, x1 = (uint32_t)tid;
        const uint32_t k0=0u, k1=42u, k2=k0^k1^0x1BD11BDAu;
        x0+=k0; x1+=k1;
        #define TFR(r) { x0+=x1; x1=rotl32(x1,r); x1^=x0; }
        TFR(13)TFR(15)TFR(26)TFR(6)   x0+=k1; x1+=k2+1u;
        TFR(17)TFR(29)TFR(16)TFR(24)  x0+=k2; x1+=k0+2u;
        TFR(13)TFR(15)TFR(26)TFR(6)   x0+=k0; x1+=k1+3u;
        TFR(17)TFR(29)TFR(16)TFR(24)  x0+=k1; x1+=k2+4u;
        TFR(13)TFR(15)TFR(26)TFR(6)   x0+=k2; x1+=k0+5u;
        #undef TFR
        g[tid] = gumbel_from_bits(x0 ^ x1);
    }
    __syncthreads();
    if (tid < BNUM){
        float z[8];
        #pragma unroll
        for (int r=0;r<8;r++) z[r] = logits[tid*8+r] + g[tid*8+r];  // TAU=1
        float mx = z[0]; int am = 0;
        #pragma unroll
        for (int r=1;r<8;r++) if (z[r] > mx){ mx=z[r]; am=r; }
        float sum=0.f;
        #pragma unroll
        for (int r=0;r<8;r++) sum += expf(z[r]-mx);
        float y = 1.0f/sum;
        wsel[tid] = (1.0f - y) + y;
        sreg[tid] = am;
    }
    __syncthreads();
    if (tid == 0){
        int cnt[RNUM];
        #pragma unroll
        for (int r=0;r<RNUM;r++) cnt[r]=0;
        for (int b=0;b<BNUM;b++){
            int r = sreg[b];
            rlist[r*BNUM + cnt[r]] = b;
            cnt[r]++;
        }
        #pragma unroll
        for (int r=0;r<RNUM;r++) rcount[r]=cnt[r];
    }
}

// ---------------- final contraction, regime-grouped, f32x2 over batch pairs ----------------
template<int NP>
__device__ __forceinline__ void fp_body(const u64* __restrict__ es2,
                                        const float* __restrict__ P,
                                        float* __restrict__ partial,
                                        const int* __restrict__ bl,
                                        int nb, int chunk, int t){
    u64 acc[NP];
    #pragma unroll
    for (int q=0;q<NP;q++) acc[q]=0ull;
    #pragma unroll 4
    for (int nh=0; nh<256; nh++){
        float pv = P[(size_t)nh*OUTC];
        u64 pp = pack2(pv, pv);
        const u64* row = es2 + nh*16;
        #pragma unroll
        for (int q=0;q<NP;q++) ffma2(acc[q], row[q], pp, acc[q]);
    }
    #pragma unroll
    for (int q=0;q<NP;q++){
        float lo, hi; unpack2(acc[q], lo, hi);
        partial[((size_t)bl[2*q]*NCHUNK + chunk)*OUTC + t] = lo;
        if (2*q+1 < nb)
            partial[((size_t)bl[2*q+1]*NCHUNK + chunk)*OUTC + t] = hi;
    }
}

__global__ void final_partial(const float* __restrict__ est, const float* __restrict__ proto,
                              const int* __restrict__ rcount, const int* __restrict__ rlist,
                              float* __restrict__ partial){
    int chunk = blockIdx.x, r = blockIdx.y, t = threadIdx.x;  // 192 threads
    int nb = rcount[r];
    if (nb == 0) return;
    int npair = (nb+1)>>1;
    __shared__ __align__(16) u64 es2[256*16];   // [nh][pair] 32KB
    __shared__ int bl[BNUM];
    if (t < BNUM) bl[t] = rlist[r*BNUM + t];
    __syncthreads();
    int nh0 = chunk*256;
    for (int q=0;q<npair;q++){
        int b0 = bl[2*q];
        bool has1 = (2*q+1) < nb;
        const float* e0 = est + (size_t)b0*NHTOT + nh0;
        const float* e1 = has1 ? est + (size_t)bl[2*q+1]*NHTOT + nh0 : e0;
        for (int nh=t; nh<256; nh+=192){
            float lo = e0[nh];
            float hi = has1 ? e1[nh] : 0.f;
            es2[nh*16+q] = pack2(lo, hi);
        }
    }
    __syncthreads();
    const float* P = proto + ((size_t)r*NHTOT + nh0)*OUTC + t;
    switch(npair){
        case 1:  fp_body<1>(es2,P,partial,bl,nb,chunk,t); break;
        case 2:  fp_body<2 >(es2,P,partial,bl,nb,chunk,t); break;
        case 3:  fp_body<3 >(es2,P,partial,bl,nb,chunk,t); break;
        case 4:  fp_body<4 >(es2,P,partial,bl,nb,chunk,t); break;
        case 5:  fp_body<5 >(es2,P,partial,bl,nb,chunk,t); break;
        case 6:  fp_body<6 >(es2,P,partial,bl,nb,chunk,t); break;
        case 7:  fp_body<7 >(es2,P,partial,bl,nb,chunk,t); break;
        case 8:  fp_body<8 >(es2,P,partial,bl,nb,chunk,t); break;
        case 9:  fp_body<9 >(es2,P,partial,bl,nb,chunk,t); break;
        case 10: fp_body<10>(es2,P,partial,bl,nb,chunk,t); break;
        case 11: fp_body<11>(es2,P,partial,bl,nb,chunk,t); break;
        case 12: fp_body<12>(es2,P,partial,bl,nb,chunk,t); break;
        case 13: fp_body<13>(es2,P,partial,bl,nb,chunk,t); break;
        case 14: fp_body<14>(es2,P,partial,bl,nb,chunk,t); break;
        case 15: fp_body<15>(es2,P,partial,bl,nb,chunk,t); break;
        default: fp_body<16>(es2,P,partial,bl,nb,chunk,t); break;
    }
}

__global__ void final_softmax(const float* __restrict__ partial, const float* __restrict__ wsel,
                              float* __restrict__ out){
    int b = blockIdx.x, t = threadIdx.x;  // 192 threads = 6 warps
    float s = 0.f;
    #pragma unroll 8
    for (int ch=0; ch<NCHUNK; ch++) s += partial[((size_t)b*NCHUNK+ch)*OUTC + t];
    s *= wsel[b];
    __shared__ float shm[6], shs[6];
    float m = s;
    #pragma unroll
    for (int o=16;o;o>>=1) m = fmaxf(m, __shfl_xor_sync(0xffffffffu, m, o));
    if ((t&31)==0) shm[t>>5]=m;
    __syncthreads();
    m = shm[0];
    #pragma unroll
    for (int w=1;w<6;w++) m = fmaxf(m, shm[w]);
    float e = expf(s-m);
    float su = e;
    #pragma unroll
    for (int o=16;o;o>>=1) su += __shfl_xor_sync(0xffffffffu, su, o);
    if ((t&31)==0) shs[t>>5]=su;
    __syncthreads();
    su = 0.f;
    #pragma unroll
    for (int w=0;w<6;w++) su += shs[w];
    out[(size_t)b*OUTC + t] = e/su;
}

// ---------------- launch ----------------
extern "C" void kernel_launch(void* const* d_in, const int* in_sizes, int n_in,
                              void* d_out, int out_size){
    (void)in_sizes; (void)n_in; (void)out_size;
    const float* in_lt = (const float*)d_in[0];
    const float* in_st = (const float*)d_in[1];
    const float* Ws  = (const float*)d_in[2];  const float* bs  = (const float*)d_in[3];
    const float* Wt  = (const float*)d_in[4];  const float* bt  = (const float*)d_in[5];
    const float* Wh1 = (const float*)d_in[6];  const float* bh1 = (const float*)d_in[7];
    const float* Wl1 = (const float*)d_in[8];  const float* bl1 = (const float*)d_in[9];
    const float* Wh2 = (const float*)d_in[10]; const float* bh2 = (const float*)d_in[11];
    const float* Wl2 = (const float*)d_in[12]; const float* bl2 = (const float*)d_in[13];
    const float* Wh3 = (const float*)d_in[14]; const float* bh3 = (const float*)d_in[15];
    const float* Wl3 = (const float*)d_in[16]; const float* bl3 = (const float*)d_in[17];
    const float* Wr  = (const float*)d_in[18]; const float* br  = (const float*)d_in[19];
    const float* proto = (const float*)d_in[20];

    float *bufA, *bufB, *est, *logits, *wsel, *partial; int *rcount, *rlist;
    cudaGetSymbolAddress((void**)&bufA,    d_bufA);
    cudaGetSymbolAddress((void**)&bufB,    d_bufB);
    cudaGetSymbolAddress((void**)&est,     d_est);
    cudaGetSymbolAddress((void**)&logits,  d_logits);
    cudaGetSymbolAddress((void**)&wsel,    d_wsel);
    cudaGetSymbolAddress((void**)&rcount,  d_rcount);
    cudaGetSymbolAddress((void**)&rlist,   d_rlist);
    cudaGetSymbolAddress((void**)&partial, d_partial);

    encode_kernel<<<dim3(LLT/4,BNUM), 128>>>(in_lt, Ws, bs, Wt, bt, bufA, LLT);
    encode_kernel<<<dim3(LST/4,BNUM), 128>>>(in_st, Ws, bs, Wt, bt, est,  LST);

    // hidden: 8 rows/block, 128 threads (R4 grid)
    hidden_kernel<<<dim3(LLT/8,BNUM), 128>>>(bufA, Wh1, bh1, bufB, LLT);
    // lookback1: G=1, 256 thr, grid (32, B)   (R4 grid)
    lookback_kernel<512,256,1><<<dim3(32,BNUM), 256>>>(bufB, Wl1, bl1, bufA);
    hidden_kernel<<<dim3(256/8,BNUM), 128>>>(bufA, Wh2, bh2, bufB, 256);
    // lookback2: G=2, 256 thr, grid (16, B)
    lookback_kernel<256,128,2><<<dim3(16,BNUM), 256>>>(bufB, Wl2, bl2, bufA);
    hidden_kernel<<<dim3(128/8,BNUM), 128>>>(bufA, Wh3, bh3, bufB, 128);
    // lookback3: G=4, 256 thr, grid (8, B)
    lookback_kernel<128,64,4><<<dim3(8,BNUM), 256>>>(bufB, Wl3, bl3, bufA);

    logits_kernel<<<BNUM, 256>>>(bufA, Wr, br, logits);
    gumbel_kernel<<<1, 256>>>(logits, wsel, rcount, rlist);

    final_partial<<<dim3(NCHUNK,RNUM), OUTC>>>(est, proto, rcount, rlist, partial);
    final_softmax<<<BNUM, OUTC>>>(partial, wsel, (float*)d_out);
}

// round 9
// speedup vs baseline: 1.3676x; 1.1803x over previous
#include <cuda_runtime.h>
#include <math.h>
#include <stdint.h>

#define BNUM 32
#define LLT 512
#define LST 128
#define CIN 9
#define HDIM 128
#define RNUM 8
#define KWIN 25
#define PADW 12
#define EPSF 1e-5f
#define OUTC 192   // M*3
#define NHTOT 16384  // LST*HDIM
#define NCHUNK 64    // nh chunks of 256

typedef unsigned long long u64;

// -------- scratch (static device, no allocs) --------
__device__ float d_bufA[BNUM*LLT*HDIM];
__device__ float d_bufB[BNUM*LLT*HDIM];
__device__ float d_est [BNUM*LST*HDIM];
__device__ float d_gbuf[4*BNUM*HDIM*256];   // raw GEMM out / K-split partials, 16MB
__device__ float d_logits[BNUM*RNUM];
__device__ float d_wsel[BNUM];
__device__ int   d_rcount[RNUM];
__device__ int   d_rlist[RNUM*BNUM];
__device__ float d_partial[BNUM*NCHUNK*OUTC];

// -------- f32x2 packed math helpers --------
__device__ __forceinline__ u64 pack2(float lo, float hi){
    u64 d;
    asm("mov.b64 %0, {%1, %2};" : "=l"(d)
        : "r"(__float_as_uint(lo)), "r"(__float_as_uint(hi)));
    return d;
}
__device__ __forceinline__ void unpack2(u64 v, float& lo, float& hi){
    uint32_t a, b;
    asm("mov.b64 {%0, %1}, %2;" : "=r"(a), "=r"(b) : "l"(v));
    lo = __uint_as_float(a); hi = __uint_as_float(b);
}
__device__ __forceinline__ void ffma2(u64& d, u64 a, u64 b, u64 c){
    asm("fma.rn.f32x2 %0, %1, %2, %3;" : "=l"(d) : "l"(a), "l"(b), "l"(c));
}

__device__ __forceinline__ float gelu_exact(float x){
    return 0.5f*x*(1.0f+erff(x*0.7071067811865476f));
}

// reduce 4 values over the NQ threads of each tid-contiguous group (NQ = 32/64/128/256)
template<int NQ>
__device__ __forceinline__ void grp_reduce4(float v[4], float* buf, int tid){
    #pragma unroll
    for (int i=0;i<4;i++){
        #pragma unroll
        for (int o=16; o; o>>=1) v[i] += __shfl_xor_sync(0xffffffffu, v[i], o);
    }
    if (NQ > 32){
        constexpr int NWG = NQ/32;
        int wid = tid>>5, lane = tid&31;
        if (lane==0){
            #pragma unroll
            for (int i=0;i<4;i++) buf[wid*4+i] = v[i];
        }
        __syncthreads();
        int gw0 = (wid/NWG)*NWG;
        #pragma unroll
        for (int i=0;i<4;i++){
            float s = 0.f;
            #pragma unroll
            for (int w=0;w<NWG;w++) s += buf[(gw0+w)*4+i];
            v[i] = s;
        }
        __syncthreads();
    }
}

// ---------------- encode: warp-per-l ----------------
__global__ void encode_kernel(const float* __restrict__ in,
                              const float* __restrict__ Ws, const float* __restrict__ bs,
                              const float* __restrict__ Wt, const float* __restrict__ bt,
                              float* __restrict__ out, int L){
    int b = blockIdx.y;
    int w = threadIdx.x >> 5, lane = threadIdx.x & 31;
    int l = blockIdx.x*4 + w;
    const float* base = in + (size_t)b*L*CIN;
    float sxl = 0.f, txl = 0.f;
    if (lane < CIN){
        int c = lane;
        float x0 = base[c];
        float xl = base[l*CIN + c];
        float sum = 0.f;
        #pragma unroll
        for (int k=0; k<KWIN; k++){
            int l2 = l - PADW + k;
            l2 = l2 < 0 ? 0 : (l2 > L-1 ? L-1 : l2);
            sum += base[l2*CIN + c];
        }
        float mavg = sum*(1.0f/KWIN);
        sxl = xl - mavg;
        txl = mavg - x0;
    }
    float sx[CIN], tx[CIN];
    #pragma unroll
    for (int c=0;c<CIN;c++){
        sx[c] = __shfl_sync(0xffffffffu, sxl, c);
        tx[c] = __shfl_sync(0xffffffffu, txl, c);
    }
    int h0 = lane*4;
    float4 bsv = *(const float4*)(bs + h0);
    float4 btv = *(const float4*)(bt + h0);
    float s4[4] = {bsv.x, bsv.y, bsv.z, bsv.w};
    float t4[4] = {btv.x, btv.y, btv.z, btv.w};
    #pragma unroll
    for (int c=0;c<CIN;c++){
        float4 wsv = *(const float4*)(Ws + c*HDIM + h0);
        float4 wtv = *(const float4*)(Wt + c*HDIM + h0);
        s4[0]=fmaf(sx[c],wsv.x,s4[0]); s4[1]=fmaf(sx[c],wsv.y,s4[1]);
        s4[2]=fmaf(sx[c],wsv.z,s4[2]); s4[3]=fmaf(sx[c],wsv.w,s4[3]);
        t4[0]=fmaf(tx[c],wtv.x,t4[0]); t4[1]=fmaf(tx[c],wtv.y,t4[1]);
        t4[2]=fmaf(tx[c],wtv.z,t4[2]); t4[3]=fmaf(tx[c],wtv.w,t4[3]);
    }
    float ss = s4[0]+s4[1]+s4[2]+s4[3];
    float ts = t4[0]+t4[1]+t4[2]+t4[3];
    #pragma unroll
    for (int o=16;o;o>>=1){
        ss += __shfl_xor_sync(0xffffffffu, ss, o);
        ts += __shfl_xor_sync(0xffffffffu, ts, o);
    }
    float ms = ss*(1.0f/HDIM), mt = ts*(1.0f/HDIM);
    float ds[4], dt[4];
    float sqs = 0.f, sqt = 0.f;
    #pragma unroll
    for (int i=0;i<4;i++){
        ds[i]=s4[i]-ms; dt[i]=t4[i]-mt;
        sqs = fmaf(ds[i],ds[i],sqs); sqt = fmaf(dt[i],dt[i],sqt);
    }
    #pragma unroll
    for (int o=16;o;o>>=1){
        sqs += __shfl_xor_sync(0xffffffffu, sqs, o);
        sqt += __shfl_xor_sync(0xffffffffu, sqt, o);
    }
    float rs = rsqrtf(sqs*(1.0f/HDIM)+EPSF);
    float rt = rsqrtf(sqt*(1.0f/HDIM)+EPSF);
    float4 y;
    y.x = gelu_exact(ds[0]*rs) + gelu_exact(dt[0]*rt);
    y.y = gelu_exact(ds[1]*rs) + gelu_exact(dt[1]*rt);
    y.z = gelu_exact(ds[2]*rs) + gelu_exact(dt[2]*rt);
    y.w = gelu_exact(ds[3]*rs) + gelu_exact(dt[3]*rt);
    *(float4*)(out + ((size_t)b*L + l)*HDIM + h0) = y;
}

// ================ generic double-buffered tiled GEMM ================
// D_z[m][n] = sum_k A_b[k][m] * B[k][n]   (no bias; finalize adds it)
// TRANSA=0 (lookback): A_b[k][m] = A[b*K*M + k*M + m]       (M=HDIM, N=LOUT, K=LIN)
// TRANSA=1 (hidden):   A_b[k][m] = A[b*M*K + m*K + k]       (M=L, N=HDIM, K=HDIM)
// D layout: TRANSA=0 -> D[(ks*BNUM+b)*M*N + m*N + n]; TRANSA=1 -> D[b*M*N + m*N + n]
template<int M, int N, int K, int TRANSA, int KS>
__global__ __launch_bounds__(256) void gemm_kernel(const float* __restrict__ A,
                                                   const float* __restrict__ B,
                                                   float* __restrict__ D){
    constexpr int MT=64, NT=64, KT=16;
    constexpr int KC = K/KS;
    constexpr int NKT = KC/KT;
    constexpr int AST = MT+4;            // padded row stride for As
    __shared__ __align__(16) float As[2][KT*AST];
    __shared__ __align__(16) float Bs[2][KT*NT];
    int tid = threadIdx.x;
    int tn = tid & 15, tm = tid >> 4;    // n-quad, m-quad
    int m0 = blockIdx.x * MT, n0 = blockIdx.y * NT;
    int z = blockIdx.z;
    int b = z / KS, ks = z % KS;
    int k0 = ks * KC;
    const float* Ab = A + (size_t)b*M*K;
    // fill index helpers
    int fk = tid >> 4, ff = tid & 15;    // row / quad within row (As T0, Bs)
    int fm = tid >> 2, fq = tid & 3;     // As T1: m-row / k-quad

    // ---- prologue: tile 0 ----
    {
        float4 pa, pb;
        if (TRANSA == 0)
            pa = *(const float4*)(Ab + (size_t)(k0 + fk)*M + m0 + 4*ff);
        else
            pa = *(const float4*)(Ab + (size_t)(m0 + fm)*K + k0 + 4*fq);
        pb = *(const float4*)(B + (size_t)(k0 + fk)*N + n0 + 4*ff);
        if (TRANSA == 0){
            *(float4*)(As[0] + fk*AST + 4*ff) = pa;
        } else {
            As[0][(4*fq+0)*AST + fm] = pa.x;
            As[0][(4*fq+1)*AST + fm] = pa.y;
            As[0][(4*fq+2)*AST + fm] = pa.z;
            As[0][(4*fq+3)*AST + fm] = pa.w;
        }
        *(float4*)(Bs[0] + fk*NT + 4*ff) = pb;
    }
    __syncthreads();

    u64 acc[4][2];
    #pragma unroll
    for (int mi=0;mi<4;mi++){ acc[mi][0]=0ull; acc[mi][1]=0ull; }

    for (int kt=0; kt<NKT; kt++){
        int cur = kt & 1;
        bool hasnext = (kt+1 < NKT);
        float4 pa, pb;
        if (hasnext){
            int kn = k0 + (kt+1)*KT;
            if (TRANSA == 0)
                pa = *(const float4*)(Ab + (size_t)(kn + fk)*M + m0 + 4*ff);
            else
                pa = *(const float4*)(Ab + (size_t)(m0 + fm)*K + kn + 4*fq);
            pb = *(const float4*)(B + (size_t)(kn + fk)*N + n0 + 4*ff);
        }
        const float* Asb = As[cur];
        const float* Bsb = Bs[cur];
        float4 av = *(const float4*)(Asb + 4*tm);
        float4 bv = *(const float4*)(Bsb + 4*tn);
        #pragma unroll
        for (int kk=0; kk<KT; kk++){
            float4 an = av, bn = bv;
            if (kk < KT-1){
                an = *(const float4*)(Asb + (kk+1)*AST + 4*tm);
                bn = *(const float4*)(Bsb + (kk+1)*NT + 4*tn);
            }
            u64 b01 = pack2(bv.x, bv.y);
            u64 b23 = pack2(bv.z, bv.w);
            u64 a0 = pack2(av.x, av.x);
            u64 a1 = pack2(av.y, av.y);
            u64 a2 = pack2(av.z, av.z);
            u64 a3 = pack2(av.w, av.w);
            ffma2(acc[0][0], a0, b01, acc[0][0]);
            ffma2(acc[0][1], a0, b23, acc[0][1]);
            ffma2(acc[1][0], a1, b01, acc[1][0]);
            ffma2(acc[1][1], a1, b23, acc[1][1]);
            ffma2(acc[2][0], a2, b01, acc[2][0]);
            ffma2(acc[2][1], a2, b23, acc[2][1]);
            ffma2(acc[3][0], a3, b01, acc[3][0]);
            ffma2(acc[3][1], a3, b23, acc[3][1]);
            av = an; bv = bn;
        }
        if (hasnext){
            int nxt = cur ^ 1;
            if (TRANSA == 0){
                *(float4*)(As[nxt] + fk*AST + 4*ff) = pa;
            } else {
                As[nxt][(4*fq+0)*AST + fm] = pa.x;
                As[nxt][(4*fq+1)*AST + fm] = pa.y;
                As[nxt][(4*fq+2)*AST + fm] = pa.z;
                As[nxt][(4*fq+3)*AST + fm] = pa.w;
            }
            *(float4*)(Bs[nxt] + fk*NT + 4*ff) = pb;
            __syncthreads();
        }
    }
    float* Dz = D + (size_t)(TRANSA ? b : (ks*BNUM + b)) * M * N;
    #pragma unroll
    for (int mi=0; mi<4; mi++){
        float4 o;
        unpack2(acc[mi][0], o.x, o.y);
        unpack2(acc[mi][1], o.z, o.w);
        *(float4*)(Dz + (size_t)(m0 + 4*tm + mi)*N + n0 + 4*tn) = o;
    }
}

// ---------------- lookback finalize: sum partials + bias, inorm over j, gelu, transpose ----------------
template<int LOUT, int KS>
__global__ void lookback_finalize(const float* __restrict__ part, const float* __restrict__ bias,
                                  float* __restrict__ out){
    int t = threadIdx.x;          // t = j, blockDim = LOUT
    int h0 = blockIdx.x*4;
    int b  = blockIdx.y;
    __shared__ float rbuf[(LOUT/32)*4];
    float bj = bias[t];
    float val[4];
    #pragma unroll
    for (int h=0;h<4;h++){
        float s = bj;
        #pragma unroll
        for (int ks=0;ks<KS;ks++)
            s += part[((size_t)(ks*BNUM + b)*HDIM + h0 + h)*LOUT + t];
        val[h]=s;
    }
    float v[4] = {val[0],val[1],val[2],val[3]};
    grp_reduce4<LOUT>(v, rbuf, t);
    float d[4];
    #pragma unroll
    for (int h=0;h<4;h++) d[h] = val[h] - v[h]*(1.0f/LOUT);
    float v2[4] = {d[0]*d[0], d[1]*d[1], d[2]*d[2], d[3]*d[3]};
    grp_reduce4<LOUT>(v2, rbuf, t);
    float4 o;
    o.x = gelu_exact(d[0]*rsqrtf(v2[0]*(1.0f/LOUT)+EPSF));
    o.y = gelu_exact(d[1]*rsqrtf(v2[1]*(1.0f/LOUT)+EPSF));
    o.z = gelu_exact(d[2]*rsqrtf(v2[2]*(1.0f/LOUT)+EPSF));
    o.w = gelu_exact(d[3]*rsqrtf(v2[3]*(1.0f/LOUT)+EPSF));
    *(float4*)(out + ((size_t)b*LOUT + t)*HDIM + h0) = o;
}

// ---------------- hidden finalize: + bias, inorm over j (=128), gelu, same layout ----------------
__global__ void hidden_finalize(const float* __restrict__ Din, const float* __restrict__ bias,
                                float* __restrict__ out, int M){
    int t = threadIdx.x;          // j 0..127
    int i0 = blockIdx.x*4;
    int b  = blockIdx.y;
    __shared__ float rbuf[4*4];
    const float* Db = Din + (size_t)b*M*HDIM;
    float bj = bias[t];
    float val[4];
    #pragma unroll
    for (int r=0;r<4;r++) val[r] = Db[(size_t)(i0+r)*HDIM + t] + bj;
    float v[4] = {val[0],val[1],val[2],val[3]};
    grp_reduce4<HDIM>(v, rbuf, t);
    float d[4];
    #pragma unroll
    for (int r=0;r<4;r++) d[r] = val[r] - v[r]*(1.0f/HDIM);
    float v2[4] = {d[0]*d[0], d[1]*d[1], d[2]*d[2], d[3]*d[3]};
    grp_reduce4<HDIM>(v2, rbuf, t);
    float* ob = out + (size_t)b*M*HDIM;
    #pragma unroll
    for (int r=0;r<4;r++)
        ob[(size_t)(i0+r)*HDIM + t] = gelu_exact(d[r]*rsqrtf(v2[r]*(1.0f/HDIM)+EPSF));
}

// ---------------- logits ----------------
__global__ void logits_kernel(const float* __restrict__ o, const float* __restrict__ Wr,
                              const float* __restrict__ br, float* __restrict__ logits){
    int b = blockIdx.x, tid = threadIdx.x;  // 256 threads
    float acc[8];
    #pragma unroll
    for (int r=0;r<8;r++) acc[r]=0.f;
    for (int i=tid; i<8192; i+=256){
        float x = o[(size_t)b*8192 + i];
        const float4* w4 = reinterpret_cast<const float4*>(Wr + (size_t)i*8);
        float4 wa = w4[0], wb = w4[1];
        acc[0]=fmaf(x,wa.x,acc[0]); acc[1]=fmaf(x,wa.y,acc[1]);
        acc[2]=fmaf(x,wa.z,acc[2]); acc[3]=fmaf(x,wa.w,acc[3]);
        acc[4]=fmaf(x,wb.x,acc[4]); acc[5]=fmaf(x,wb.y,acc[5]);
        acc[6]=fmaf(x,wb.z,acc[6]); acc[7]=fmaf(x,wb.w,acc[7]);
    }
    __shared__ float sh[8*8];
    #pragma unroll
    for (int r=0;r<8;r++){
        #pragma unroll
        for (int o2=16;o2;o2>>=1) acc[r] += __shfl_xor_sync(0xffffffffu, acc[r], o2);
    }
    int w=tid>>5, lane=tid&31;
    if (lane==0){
        #pragma unroll
        for (int r=0;r<8;r++) sh[r*8+w]=acc[r];
    }
    __syncthreads();
    if (tid<8){
        float s=br[tid];
        #pragma unroll
        for (int ww=0;ww<8;ww++) s+=sh[tid*8+ww];
        logits[b*8+tid]=s;
    }
}

// ---------------- exact JAX threefry2x32 (partitionable) gumbel + regime lists ----------------
__device__ __forceinline__ uint32_t rotl32(uint32_t x,int r){ return (x<<r)|(x>>(32-r)); }
__device__ __forceinline__ float gumbel_from_bits(uint32_t bits){
    const float tiny = 1.17549435e-38f;
    float f = __uint_as_float((bits>>9)|0x3f800000u) - 1.0f;
    float u = fmaxf(tiny, f + tiny);
    return -logf(-logf(u));
}
__global__ void gumbel_kernel(const float* __restrict__ logits,
                              float* __restrict__ wsel,
                              int* __restrict__ rcount, int* __restrict__ rlist){
    __shared__ float g[256];
    __shared__ int sreg[BNUM];
    int tid = threadIdx.x;  // 256 threads
    {
        uint32_t x0 = 0u, x1 = (uint32_t)tid;
        const uint32_t k0=0u, k1=42u, k2=k0^k1^0x1BD11BDAu;
        x0+=k0; x1+=k1;
        #define TFR(r) { x0+=x1; x1=rotl32(x1,r); x1^=x0; }
        TFR(13)TFR(15)TFR(26)TFR(6)   x0+=k1; x1+=k2+1u;
        TFR(17)TFR(29)TFR(16)TFR(24)  x0+=k2; x1+=k0+2u;
        TFR(13)TFR(15)TFR(26)TFR(6)   x0+=k0; x1+=k1+3u;
        TFR(17)TFR(29)TFR(16)TFR(24)  x0+=k1; x1+=k2+4u;
        TFR(13)TFR(15)TFR(26)TFR(6)   x0+=k2; x1+=k0+5u;
        #undef TFR
        g[tid] = gumbel_from_bits(x0 ^ x1);
    }
    __syncthreads();
    if (tid < BNUM){
        float z[8];
        #pragma unroll
        for (int r=0;r<8;r++) z[r] = logits[tid*8+r] + g[tid*8+r];  // TAU=1
        float mx = z[0]; int am = 0;
        #pragma unroll
        for (int r=1;r<8;r++) if (z[r] > mx){ mx=z[r]; am=r; }
        float sum=0.f;
        #pragma unroll
        for (int r=0;r<8;r++) sum += expf(z[r]-mx);
        float y = 1.0f/sum;
        wsel[tid] = (1.0f - y) + y;
        sreg[tid] = am;
    }
    __syncthreads();
    if (tid == 0){
        int cnt[RNUM];
        #pragma unroll
        for (int r=0;r<RNUM;r++) cnt[r]=0;
        for (int b=0;b<BNUM;b++){
            int r = sreg[b];
            rlist[r*BNUM + cnt[r]] = b;
            cnt[r]++;
        }
        #pragma unroll
        for (int r=0;r<RNUM;r++) rcount[r]=cnt[r];
    }
}

// ---------------- final contraction, regime-grouped, f32x2 over batch pairs ----------------
template<int NP>
__device__ __forceinline__ void fp_body(const u64* __restrict__ es2,
                                        const float* __restrict__ P,
                                        float* __restrict__ partial,
                                        const int* __restrict__ bl,
                                        int nb, int chunk, int t){
    u64 acc[NP];
    #pragma unroll
    for (int q=0;q<NP;q++) acc[q]=0ull;
    #pragma unroll 4
    for (int nh=0; nh<256; nh++){
        float pv = P[(size_t)nh*OUTC];
        u64 pp = pack2(pv, pv);
        const u64* row = es2 + nh*16;
        #pragma unroll
        for (int q=0;q<NP;q++) ffma2(acc[q], row[q], pp, acc[q]);
    }
    #pragma unroll
    for (int q=0;q<NP;q++){
        float lo, hi; unpack2(acc[q], lo, hi);
        partial[((size_t)bl[2*q]*NCHUNK + chunk)*OUTC + t] = lo;
        if (2*q+1 < nb)
            partial[((size_t)bl[2*q+1]*NCHUNK + chunk)*OUTC + t] = hi;
    }
}

__global__ void final_partial(const float* __restrict__ est, const float* __restrict__ proto,
                              const int* __restrict__ rcount, const int* __restrict__ rlist,
                              float* __restrict__ partial){
    int chunk = blockIdx.x, r = blockIdx.y, t = threadIdx.x;  // 192 threads
    int nb = rcount[r];
    if (nb == 0) return;
    int npair = (nb+1)>>1;
    __shared__ __align__(16) u64 es2[256*16];   // [nh][pair] 32KB
    __shared__ int bl[BNUM];
    if (t < BNUM) bl[t] = rlist[r*BNUM + t];
    __syncthreads();
    int nh0 = chunk*256;
    for (int q=0;q<npair;q++){
        int b0 = bl[2*q];
        bool has1 = (2*q+1) < nb;
        const float* e0 = est + (size_t)b0*NHTOT + nh0;
        const float* e1 = has1 ? est + (size_t)bl[2*q+1]*NHTOT + nh0 : e0;
        for (int nh=t; nh<256; nh+=192){
            float lo = e0[nh];
            float hi = has1 ? e1[nh] : 0.f;
            es2[nh*16+q] = pack2(lo, hi);
        }
    }
    __syncthreads();
    const float* P = proto + ((size_t)r*NHTOT + nh0)*OUTC + t;
    switch(npair){
        case 1:  fp_body<1>(es2,P,partial,bl,nb,chunk,t); break;
        case 2:  fp_body<2 >(es2,P,partial,bl,nb,chunk,t); break;
        case 3:  fp_body<3 >(es2,P,partial,bl,nb,chunk,t); break;
        case 4:  fp_body<4 >(es2,P,partial,bl,nb,chunk,t); break;
        case 5:  fp_body<5 >(es2,P,partial,bl,nb,chunk,t); break;
        case 6:  fp_body<6 >(es2,P,partial,bl,nb,chunk,t); break;
        case 7:  fp_body<7 >(es2,P,partial,bl,nb,chunk,t); break;
        case 8:  fp_body<8 >(es2,P,partial,bl,nb,chunk,t); break;
        case 9:  fp_body<9 >(es2,P,partial,bl,nb,chunk,t); break;
        case 10: fp_body<10>(es2,P,partial,bl,nb,chunk,t); break;
        case 11: fp_body<11>(es2,P,partial,bl,nb,chunk,t); break;
        case 12: fp_body<12>(es2,P,partial,bl,nb,chunk,t); break;
        case 13: fp_body<13>(es2,P,partial,bl,nb,chunk,t); break;
        case 14: fp_body<14>(es2,P,partial,bl,nb,chunk,t); break;
        case 15: fp_body<15>(es2,P,partial,bl,nb,chunk,t); break;
        default: fp_body<16>(es2,P,partial,bl,nb,chunk,t); break;
    }
}

__global__ void final_softmax(const float* __restrict__ partial, const float* __restrict__ wsel,
                              float* __restrict__ out){
    int b = blockIdx.x, t = threadIdx.x;  // 192 threads = 6 warps
    float s = 0.f;
    #pragma unroll 8
    for (int ch=0; ch<NCHUNK; ch++) s += partial[((size_t)b*NCHUNK+ch)*OUTC + t];
    s *= wsel[b];
    __shared__ float shm[6], shs[6];
    float m = s;
    #pragma unroll
    for (int o=16;o;o>>=1) m = fmaxf(m, __shfl_xor_sync(0xffffffffu, m, o));
    if ((t&31)==0) shm[t>>5]=m;
    __syncthreads();
    m = shm[0];
    #pragma unroll
    for (int w=1;w<6;w++) m = fmaxf(m, shm[w]);
    float e = expf(s-m);
    float su = e;
    #pragma unroll
    for (int o=16;o;o>>=1) su += __shfl_xor_sync(0xffffffffu, su, o);
    if ((t&31)==0) shs[t>>5]=su;
    __syncthreads();
    su = 0.f;
    #pragma unroll
    for (int w=0;w<6;w++) su += shs[w];
    out[(size_t)b*OUTC + t] = e/su;
}

// ---------------- launch ----------------
extern "C" void kernel_launch(void* const* d_in, const int* in_sizes, int n_in,
                              void* d_out, int out_size){
    (void)in_sizes; (void)n_in; (void)out_size;
    const float* in_lt = (const float*)d_in[0];
    const float* in_st = (const float*)d_in[1];
    const float* Ws  = (const float*)d_in[2];  const float* bs  = (const float*)d_in[3];
    const float* Wt  = (const float*)d_in[4];  const float* bt  = (const float*)d_in[5];
    const float* Wh1 = (const float*)d_in[6];  const float* bh1 = (const float*)d_in[7];
    const float* Wl1 = (const float*)d_in[8];  const float* bl1 = (const float*)d_in[9];
    const float* Wh2 = (const float*)d_in[10]; const float* bh2 = (const float*)d_in[11];
    const float* Wl2 = (const float*)d_in[12]; const float* bl2 = (const float*)d_in[13];
    const float* Wh3 = (const float*)d_in[14]; const float* bh3 = (const float*)d_in[15];
    const float* Wl3 = (const float*)d_in[16]; const float* bl3 = (const float*)d_in[17];
    const float* Wr  = (const float*)d_in[18]; const float* br  = (const float*)d_in[19];
    const float* proto = (const float*)d_in[20];

    float *bufA, *bufB, *est, *gbuf, *logits, *wsel, *partial; int *rcount, *rlist;
    cudaGetSymbolAddress((void**)&bufA,    d_bufA);
    cudaGetSymbolAddress((void**)&bufB,    d_bufB);
    cudaGetSymbolAddress((void**)&est,     d_est);
    cudaGetSymbolAddress((void**)&gbuf,    d_gbuf);
    cudaGetSymbolAddress((void**)&logits,  d_logits);
    cudaGetSymbolAddress((void**)&wsel,    d_wsel);
    cudaGetSymbolAddress((void**)&rcount,  d_rcount);
    cudaGetSymbolAddress((void**)&rlist,   d_rlist);
    cudaGetSymbolAddress((void**)&partial, d_partial);

    encode_kernel<<<dim3(LLT/4,BNUM), 128>>>(in_lt, Ws, bs, Wt, bt, bufA, LLT);
    encode_kernel<<<dim3(LST/4,BNUM), 128>>>(in_st, Ws, bs, Wt, bt, est,  LST);

    // hidden1: M=512, N=128, K=128, TRANSA=1
    gemm_kernel<512,128,128,1,1><<<dim3(8,2,BNUM), 256>>>(bufA, Wh1, gbuf);
    hidden_finalize<<<dim3(512/4,BNUM), 128>>>(gbuf, bh1, bufB, 512);
    // lookback1: M=128(h), N=256(j), K=512(l), KS=2
    gemm_kernel<128,256,512,0,2><<<dim3(2,4,BNUM*2), 256>>>(bufB, Wl1, gbuf);
    lookback_finalize<256,2><<<dim3(HDIM/4,BNUM), 256>>>(gbuf, bl1, bufA);

    // hidden2: M=256
    gemm_kernel<256,128,128,1,1><<<dim3(4,2,BNUM), 256>>>(bufA, Wh2, gbuf);
    hidden_finalize<<<dim3(256/4,BNUM), 128>>>(gbuf, bh2, bufB, 256);
    // lookback2: N=128, K=256
    gemm_kernel<128,128,256,0,1><<<dim3(2,2,BNUM), 256>>>(bufB, Wl2, gbuf);
    lookback_finalize<128,1><<<dim3(HDIM/4,BNUM), 128>>>(gbuf, bl2, bufA);

    // hidden3: M=128
    gemm_kernel<128,128,128,1,1><<<dim3(2,2,BNUM), 256>>>(bufA, Wh3, gbuf);
    hidden_finalize<<<dim3(128/4,BNUM), 128>>>(gbuf, bh3, bufB, 128);
    // lookback3: N=64, K=128
    gemm_kernel<128,64,128,0,1><<<dim3(2,1,BNUM), 256>>>(bufB, Wl3, gbuf);
    lookback_finalize<64,1><<<dim3(HDIM/4,BNUM), 64>>>(gbuf, bl3, bufA);

    logits_kernel<<<BNUM, 256>>>(bufA, Wr, br, logits);
    gumbel_kernel<<<1, 256>>>(logits, wsel, rcount, rlist);

    final_partial<<<dim3(NCHUNK,RNUM), OUTC>>>(est, proto, rcount, rlist, partial);
    final_softmax<<<BNUM, OUTC>>>(partial, wsel, (float*)d_out);
}